// round 5
// baseline (speedup 1.0000x reference)
#include <cuda_runtime.h>
#include <cuda_bf16.h>
#include <cuda_fp16.h>
#include <math.h>
#include <stdint.h>

#define B_  2
#define T_  4096
#define C_  768
#define H_  12
#define D_  64
#define NQKV_ 2304
#define M_  8192
#define BH_ (B_*H_)

typedef __nv_bfloat16 bf16;

// ---------------- device scratch (allocation-free rule) -------------------
__device__ __align__(16) bf16 g_xh[M_*C_],      g_xl[M_*C_];
__device__ __align__(16) bf16 g_wqkvT_h[NQKV_*C_], g_wqkvT_l[NQKV_*C_];
__device__ __align__(16) bf16 g_wpT_h[C_*C_],   g_wpT_l[C_*C_];
__device__ __align__(16) bf16 g_Qh[BH_*T_*D_],  g_Ql[BH_*T_*D_];
__device__ __align__(16) bf16 g_Kh[BH_*T_*D_],  g_Kl[BH_*T_*D_];
__device__ __align__(16) __half g_Vt[BH_*D_*T_];          // [bh][d][t], single fp16
__device__ __align__(16) bf16 g_Yh[M_*C_],      g_Yl[M_*C_];

// ---------------- helpers -------------------------------------------------
__device__ __forceinline__ void mma16816(float c[4], const uint32_t a[4], const uint32_t b[2]) {
    asm volatile("mma.sync.aligned.m16n8k16.row.col.f32.bf16.bf16.f32 "
        "{%0,%1,%2,%3}, {%4,%5,%6,%7}, {%8,%9}, {%0,%1,%2,%3};\n"
        : "+f"(c[0]), "+f"(c[1]), "+f"(c[2]), "+f"(c[3])
        : "r"(a[0]), "r"(a[1]), "r"(a[2]), "r"(a[3]), "r"(b[0]), "r"(b[1]));
}
__device__ __forceinline__ void mma16816h(float c[4], const uint32_t a[4], const uint32_t b[2]) {
    asm volatile("mma.sync.aligned.m16n8k16.row.col.f32.f16.f16.f32 "
        "{%0,%1,%2,%3}, {%4,%5,%6,%7}, {%8,%9}, {%0,%1,%2,%3};\n"
        : "+f"(c[0]), "+f"(c[1]), "+f"(c[2]), "+f"(c[3])
        : "r"(a[0]), "r"(a[1]), "r"(a[2]), "r"(a[3]), "r"(b[0]), "r"(b[1]));
}
// warp-collective: 4x (8x8 b16) tiles, per-lane address
__device__ __forceinline__ void ldsm4(uint32_t r[4], const void* p) {
    uint32_t a = (uint32_t)__cvta_generic_to_shared(p);
    asm volatile("ldmatrix.sync.aligned.m8n8.x4.shared.b16 {%0,%1,%2,%3}, [%4];"
        : "=r"(r[0]), "=r"(r[1]), "=r"(r[2]), "=r"(r[3]) : "r"(a));
}

__device__ __forceinline__ void cp16(void* dst, const void* src) {
    unsigned d = (unsigned)__cvta_generic_to_shared(dst);
    asm volatile("cp.async.cg.shared.global [%0], [%1], 16;\n" :: "r"(d), "l"(src));
}
__device__ __forceinline__ void cp_commit() { asm volatile("cp.async.commit_group;\n"); }
template<int N> __device__ __forceinline__ void cp_wait() {
    asm volatile("cp.async.wait_group %0;\n" :: "n"(N));
}

__device__ __forceinline__ void split2(float v, bf16& h, bf16& l) {
    h = __float2bfloat16(v);
    l = __float2bfloat16(v - __bfloat162float(h));
}

__device__ __forceinline__ float fast_exp2(float y) {
    y = fmaxf(y, -120.f);
    float t = y + 12582912.f;
    int   yi = __float_as_int(t) - 0x4B400000;
    float f  = y - (t - 12582912.f);
    float p = 1.3333558146e-3f;
    p = fmaf(p, f, 9.6181291076e-3f);
    p = fmaf(p, f, 5.5504108664e-2f);
    p = fmaf(p, f, 2.4022650696e-1f);
    p = fmaf(p, f, 6.9314718056e-1f);
    p = fmaf(p, f, 1.0f);
    return p * __int_as_float((yi + 127) << 23);
}

__device__ __forceinline__ void pack_split(float a, float b, uint32_t& ph, uint32_t& pl) {
    bf16 ah, al, bh, bl;
    split2(a, ah, al); split2(b, bh, bl);
    __nv_bfloat162 Hh; Hh.x = ah; Hh.y = bh;
    __nv_bfloat162 Ll; Ll.x = al; Ll.y = bl;
    ph = *(uint32_t*)&Hh; pl = *(uint32_t*)&Ll;
}

// ---------------- prep kernels -------------------------------------------
__global__ __launch_bounds__(256) void split_x_kernel(const float* __restrict__ x) {
    size_t i = ((size_t)blockIdx.x * 256 + threadIdx.x) * 4;
    float4 v = *(const float4*)(x + i);
    bf16 h0,l0,h1,l1,h2,l2,h3,l3;
    split2(v.x,h0,l0); split2(v.y,h1,l1); split2(v.z,h2,l2); split2(v.w,h3,l3);
    __nv_bfloat162 a,b,c,d;
    a.x=h0; a.y=h1; b.x=h2; b.y=h3; c.x=l0; c.y=l1; d.x=l2; d.y=l3;
    *(__nv_bfloat162*)(g_xh + i)     = a;
    *(__nv_bfloat162*)(g_xh + i + 2) = b;
    *(__nv_bfloat162*)(g_xl + i)     = c;
    *(__nv_bfloat162*)(g_xl + i + 2) = d;
}

__global__ __launch_bounds__(256) void tsplit_kernel(const float* __restrict__ w,
                                                     int K, int N, int mode) {
    __shared__ float tile[32][33];
    bf16* outh = mode == 0 ? g_wqkvT_h : g_wpT_h;
    bf16* outl = mode == 0 ? g_wqkvT_l : g_wpT_l;
    const int n0 = blockIdx.x * 32, k0 = blockIdx.y * 32;
    const int tx = threadIdx.x & 31, ty = threadIdx.x >> 5;
#pragma unroll
    for (int r = 0; r < 32; r += 8)
        tile[ty + r][tx] = w[(size_t)(k0 + ty + r) * N + n0 + tx];
    __syncthreads();
#pragma unroll
    for (int r = 0; r < 32; r += 8) {
        float v = tile[tx][ty + r];
        bf16 h, l; split2(v, h, l);
        size_t o = (size_t)(n0 + ty + r) * K + k0 + tx;
        outh[o] = h; outl[o] = l;
    }
}

// ---------------- GEMM ----------------------------------------------------
__device__ __forceinline__ void epi_qkv(int m, int n, float v0, float v1) {
    const int b = m >> 12, t = m & 4095;
    const int sec = n / C_, r = n - sec * C_;
    const int h = r >> 6, d = r & 63;
    const int bh = b * H_ + h;
    if (sec == 2) {
        size_t o = ((size_t)bh * D_ + d) * T_ + t;
        g_Vt[o]      = __float2half(v0);
        g_Vt[o + T_] = __float2half(v1);
    } else {
        bf16 h0, l0, h1, l1;
        split2(v0, h0, l0); split2(v1, h1, l1);
        size_t o = ((size_t)bh * T_ + t) * D_ + d;
        bf16* dh = sec == 0 ? g_Qh : g_Kh;
        bf16* dl = sec == 0 ? g_Ql : g_Kl;
        __nv_bfloat162 Hh; Hh.x = h0; Hh.y = h1;
        __nv_bfloat162 Ll; Ll.x = l0; Ll.y = l1;
        *(__nv_bfloat162*)(dh + o) = Hh;
        *(__nv_bfloat162*)(dl + o) = Ll;
    }
}

template<int MODE>
__global__ __launch_bounds__(256, 2) void gemm_kernel(float* __restrict__ out) {
    extern __shared__ bf16 sm[];
    bf16* sAh = sm;
    bf16* sAl = sm + 2 * 5120;
    bf16* sBh = sm + 4 * 5120;
    bf16* sBl = sm + 6 * 5120;

    const bf16* Agh = (MODE == 1) ? g_xh : g_Yh;
    const bf16* Agl = (MODE == 1) ? g_xl : g_Yl;
    const bf16* Bgh = (MODE == 1) ? g_wqkvT_h : g_wpT_h;
    const bf16* Bgl = (MODE == 1) ? g_wqkvT_l : g_wpT_l;

    const int tid = threadIdx.x, wid = tid >> 5, lane = tid & 31;
    const int wm = wid >> 1, wn = wid & 1;
    const int lq = lane >> 2, cq = (lane & 3) << 1;
    const int bm = blockIdx.y * 128, bn = blockIdx.x * 128;

    // per-lane ldmatrix offsets (elements)
    const int a_loff = ((((lane >> 3) & 1) * 8 + (lane & 7)) * 40) + (lane >> 4) * 8;
    const int b_loff = (((lane >> 4) * 8 + (lane & 7)) * 40) + ((lane >> 3) & 1) * 8;

    float acc[2][8][4];
#pragma unroll
    for (int i = 0; i < 2; i++)
#pragma unroll
        for (int j = 0; j < 8; j++)
#pragma unroll
            for (int k = 0; k < 4; k++) acc[i][j][k] = 0.f;

#define LOAD_TILES(BUF, K0)                                                   \
    {                                                                         \
        _Pragma("unroll")                                                     \
        for (int i_ = 0; i_ < 2; i_++) {                                      \
            int c_ = tid + 256 * i_;                                          \
            int row_ = c_ >> 2;                                               \
            int ko_ = (c_ & 3) << 3;                                          \
            size_t ga_ = (size_t)(bm + row_) * C_ + (K0) + ko_;               \
            size_t gb_ = (size_t)(bn + row_) * C_ + (K0) + ko_;               \
            int so_ = (BUF) * 5120 + row_ * 40 + ko_;                         \
            cp16(sAh + so_, Agh + ga_);                                       \
            cp16(sAl + so_, Agl + ga_);                                       \
            cp16(sBh + so_, Bgh + gb_);                                       \
            cp16(sBl + so_, Bgl + gb_);                                       \
        }                                                                     \
    }

    LOAD_TILES(0, 0); cp_commit();
    int buf = 0;
    for (int kt = 0; kt < 24; kt++) {
        if (kt < 23) { LOAD_TILES(buf ^ 1, (kt + 1) * 32); cp_commit(); cp_wait<1>(); }
        else cp_wait<0>();
        __syncthreads();
#pragma unroll
        for (int kc = 0; kc < 2; kc++) {
            uint32_t ah[2][4], al[2][4];
#pragma unroll
            for (int mc = 0; mc < 2; mc++) {
                const int ao = buf * 5120 + (wm * 32 + mc * 16) * 40 + kc * 16 + a_loff;
                ldsm4(ah[mc], sAh + ao);
                ldsm4(al[mc], sAl + ao);
            }
#pragma unroll
            for (int nc2 = 0; nc2 < 4; nc2++) {
                uint32_t bh4[4], bl4[4];
                const int bo = buf * 5120 + (wn * 64 + nc2 * 16) * 40 + kc * 16 + b_loff;
                ldsm4(bh4, sBh + bo);
                ldsm4(bl4, sBl + bo);
#pragma unroll
                for (int mc = 0; mc < 2; mc++) {
                    mma16816(acc[mc][2*nc2],   ah[mc], &bh4[0]);
                    mma16816(acc[mc][2*nc2],   ah[mc], &bl4[0]);
                    mma16816(acc[mc][2*nc2],   al[mc], &bh4[0]);
                    mma16816(acc[mc][2*nc2+1], ah[mc], &bh4[2]);
                    mma16816(acc[mc][2*nc2+1], ah[mc], &bl4[2]);
                    mma16816(acc[mc][2*nc2+1], al[mc], &bh4[2]);
                }
            }
        }
        __syncthreads();
        buf ^= 1;
    }

#pragma unroll
    for (int mc = 0; mc < 2; mc++)
#pragma unroll
        for (int nc = 0; nc < 8; nc++) {
            const int m = bm + wm * 32 + mc * 16 + lq;
            const int n = bn + wn * 64 + nc * 8 + cq;
            float* a = acc[mc][nc];
            if (MODE == 2) {
                *(float2*)&out[(size_t)m * C_ + n]       = make_float2(a[0], a[1]);
                *(float2*)&out[(size_t)(m + 8) * C_ + n] = make_float2(a[2], a[3]);
            } else {
                epi_qkv(m, n, a[0], a[1]);
                epi_qkv(m + 8, n, a[2], a[3]);
            }
        }
}

// ---------------- flash attention -----------------------------------------
#define SA_ 0.1803368801111204f     /* 0.125 * log2(e) */
#define FSTAGE 13824
#define FLASH_SMEM (2 * FSTAGE * 2)

__global__ __launch_bounds__(256) void flash_kernel() {
    extern __shared__ bf16 fsm[];

    const int qt = (int)(gridDim.x - 1) - (int)blockIdx.x;
    const int bh = blockIdx.y;
    const int tid = threadIdx.x, wid = tid >> 5, lane = tid & 31;
    const int lq = lane >> 2, cq = (lane & 3) << 1;
    const int row0 = qt * 128 + wid * 16 + lq;

    // per-lane ldmatrix offset for B-style fragments, stride 72
    const int b_loff = (((lane >> 4) * 8 + (lane & 7)) * 72) + ((lane >> 3) & 1) * 8;

    const size_t qoff = ((size_t)bh * T_ + row0) * D_;
    uint32_t qh[4][4], ql[4][4];
#pragma unroll
    for (int kc = 0; kc < 4; kc++) {
        const int c = kc * 16 + cq;
        qh[kc][0] = *(const uint32_t*)(g_Qh + qoff + c);
        qh[kc][1] = *(const uint32_t*)(g_Qh + qoff + 8 * D_ + c);
        qh[kc][2] = *(const uint32_t*)(g_Qh + qoff + c + 8);
        qh[kc][3] = *(const uint32_t*)(g_Qh + qoff + 8 * D_ + c + 8);
        ql[kc][0] = *(const uint32_t*)(g_Ql + qoff + c);
        ql[kc][1] = *(const uint32_t*)(g_Ql + qoff + 8 * D_ + c);
        ql[kc][2] = *(const uint32_t*)(g_Ql + qoff + c + 8);
        ql[kc][3] = *(const uint32_t*)(g_Ql + qoff + 8 * D_ + c + 8);
    }

    float oacc[8][4];
#pragma unroll
    for (int i = 0; i < 8; i++)
#pragma unroll
        for (int j = 0; j < 4; j++) oacc[i][j] = 0.f;
    float m0 = -1e30f, m1 = -1e30f, l0 = 0.f, l1 = 0.f;

    const bf16* Kb_h = g_Kh + (size_t)bh * T_ * D_;
    const bf16* Kb_l = g_Kl + (size_t)bh * T_ * D_;
    const __half* Vb = g_Vt + (size_t)bh * D_ * T_;

#define LOADF(BUF, KT)                                                        \
    {                                                                         \
        bf16* bb = fsm + (BUF) * FSTAGE;                                      \
        const bf16* ph_ = Kb_h + (size_t)(KT) * 64 * D_;                      \
        const bf16* pl_ = Kb_l + (size_t)(KT) * 64 * D_;                      \
        _Pragma("unroll")                                                     \
        for (int c_ = tid; c_ < 512; c_ += 256) {                             \
            const int r_ = c_ >> 3, of_ = (c_ & 7) << 3;                      \
            cp16(bb + r_ * 72 + of_, ph_ + r_ * D_ + of_);                    \
            cp16(bb + 4608 + r_ * 72 + of_, pl_ + r_ * D_ + of_);             \
            cp16((__half*)(bb + 9216) + r_ * 72 + of_,                        \
                 Vb + (size_t)r_ * T_ + (KT) * 64 + of_);                     \
        }                                                                     \
    }

    const int nkt = 2 * qt + 2;
    LOADF(0, 0); cp_commit();
    int buf = 0;
    for (int kt = 0; kt < nkt; kt++) {
        cp_wait<0>(); __syncthreads();
        if (kt + 1 < nkt) { LOADF(buf ^ 1, kt + 1); cp_commit(); }

        const bf16* sKh = fsm + buf * FSTAGE;
        const bf16* sKl = sKh + 4608;
        const __half* sVt = (const __half*)(sKh + 9216);

        // S = Q K^T (3-term bf16 split), fragments via ldmatrix
        float sacc[8][4];
#pragma unroll
        for (int i = 0; i < 8; i++)
#pragma unroll
            for (int j = 0; j < 4; j++) sacc[i][j] = 0.f;
#pragma unroll
        for (int kc = 0; kc < 4; kc++) {
#pragma unroll
            for (int nc2 = 0; nc2 < 4; nc2++) {
                uint32_t kh4[4], kl4[4];
                const int o = nc2 * 16 * 72 + kc * 16 + b_loff;
                ldsm4(kh4, sKh + o);
                ldsm4(kl4, sKl + o);
                mma16816(sacc[2*nc2],   qh[kc], &kh4[0]);
                mma16816(sacc[2*nc2],   qh[kc], &kl4[0]);
                mma16816(sacc[2*nc2],   ql[kc], &kh4[0]);
                mma16816(sacc[2*nc2+1], qh[kc], &kh4[2]);
                mma16816(sacc[2*nc2+1], qh[kc], &kl4[2]);
                mma16816(sacc[2*nc2+1], ql[kc], &kh4[2]);
            }
        }

        // causal mask
        if (kt >= 2 * qt) {
            const int colb = kt * 64;
#pragma unroll
            for (int nc = 0; nc < 8; nc++) {
                const int c0 = colb + nc * 8 + cq;
                if (c0     > row0)     sacc[nc][0] = -1e30f;
                if (c0 + 1 > row0)     sacc[nc][1] = -1e30f;
                if (c0     > row0 + 8) sacc[nc][2] = -1e30f;
                if (c0 + 1 > row0 + 8) sacc[nc][3] = -1e30f;
            }
        }

        // online softmax
        float mx0 = -1e30f, mx1 = -1e30f;
#pragma unroll
        for (int nc = 0; nc < 8; nc++) {
            mx0 = fmaxf(mx0, fmaxf(sacc[nc][0], sacc[nc][1]));
            mx1 = fmaxf(mx1, fmaxf(sacc[nc][2], sacc[nc][3]));
        }
        mx0 = fmaxf(mx0, __shfl_xor_sync(0xffffffffu, mx0, 1));
        mx0 = fmaxf(mx0, __shfl_xor_sync(0xffffffffu, mx0, 2));
        mx1 = fmaxf(mx1, __shfl_xor_sync(0xffffffffu, mx1, 1));
        mx1 = fmaxf(mx1, __shfl_xor_sync(0xffffffffu, mx1, 2));
        const float mn0 = fmaxf(m0, mx0), mn1 = fmaxf(m1, mx1);
        const float sc0 = fast_exp2((m0 - mn0) * SA_);
        const float sc1 = fast_exp2((m1 - mn1) * SA_);
        m0 = mn0; m1 = mn1;
        l0 *= sc0; l1 *= sc1;
#pragma unroll
        for (int dc = 0; dc < 8; dc++) {
            oacc[dc][0] *= sc0; oacc[dc][1] *= sc0;
            oacc[dc][2] *= sc1; oacc[dc][3] *= sc1;
        }

        // P = exp(S - m) -> fp16 A fragments
        uint32_t pa[4][4];
#pragma unroll
        for (int kc = 0; kc < 4; kc++) {
            const float e0 = fast_exp2((sacc[2*kc][0]   - m0) * SA_);
            const float e1 = fast_exp2((sacc[2*kc][1]   - m0) * SA_);
            const float e2 = fast_exp2((sacc[2*kc][2]   - m1) * SA_);
            const float e3 = fast_exp2((sacc[2*kc][3]   - m1) * SA_);
            const float f0 = fast_exp2((sacc[2*kc+1][0] - m0) * SA_);
            const float f1 = fast_exp2((sacc[2*kc+1][1] - m0) * SA_);
            const float f2 = fast_exp2((sacc[2*kc+1][2] - m1) * SA_);
            const float f3 = fast_exp2((sacc[2*kc+1][3] - m1) * SA_);
            l0 += e0 + e1 + f0 + f1;
            l1 += e2 + e3 + f2 + f3;
            __half2 t0 = __floats2half2_rn(e0, e1);
            __half2 t1 = __floats2half2_rn(e2, e3);
            __half2 t2 = __floats2half2_rn(f0, f1);
            __half2 t3 = __floats2half2_rn(f2, f3);
            pa[kc][0] = *(uint32_t*)&t0;
            pa[kc][1] = *(uint32_t*)&t1;
            pa[kc][2] = *(uint32_t*)&t2;
            pa[kc][3] = *(uint32_t*)&t3;
        }

        // O += P V  (single fp16 mma), V fragments via ldmatrix
#pragma unroll
        for (int kc = 0; kc < 4; kc++) {
#pragma unroll
            for (int dc2 = 0; dc2 < 4; dc2++) {
                uint32_t v4[4];
                ldsm4(v4, sVt + dc2 * 16 * 72 + kc * 16 + b_loff);
                mma16816h(oacc[2*dc2],   pa[kc], &v4[0]);
                mma16816h(oacc[2*dc2+1], pa[kc], &v4[2]);
            }
        }
        __syncthreads();
        buf ^= 1;
    }

    // finalize
    l0 += __shfl_xor_sync(0xffffffffu, l0, 1);
    l0 += __shfl_xor_sync(0xffffffffu, l0, 2);
    l1 += __shfl_xor_sync(0xffffffffu, l1, 1);
    l1 += __shfl_xor_sync(0xffffffffu, l1, 2);
    const float inv0 = 1.f / l0, inv1 = 1.f / l1;

    const int b = bh / H_, h = bh - b * H_;
    const size_t y0 = ((size_t)b * T_ + row0) * C_ + h * D_;
    const size_t y1 = ((size_t)b * T_ + row0 + 8) * C_ + h * D_;
#pragma unroll
    for (int dc = 0; dc < 8; dc++) {
        const int col = dc * 8 + cq;
        uint32_t ph, pl;
        pack_split(oacc[dc][0] * inv0, oacc[dc][1] * inv0, ph, pl);
        *(uint32_t*)(g_Yh + y0 + col) = ph;
        *(uint32_t*)(g_Yl + y0 + col) = pl;
        pack_split(oacc[dc][2] * inv1, oacc[dc][3] * inv1, ph, pl);
        *(uint32_t*)(g_Yh + y1 + col) = ph;
        *(uint32_t*)(g_Yl + y1 + col) = pl;
    }
}

// ---------------------------------------------------------------------------
extern "C" void kernel_launch(void* const* d_in, const int* in_sizes, int n_in,
                              void* d_out, int out_size)
{
    const float* x      = (const float*)d_in[0];
    const float* w_qkv  = (const float*)d_in[1];
    const float* w_proj = (const float*)d_in[2];
    float* out = (float*)d_out;

    split_x_kernel<<<(M_ * C_) / (256 * 4), 256>>>(x);
    tsplit_kernel<<<dim3(NQKV_ / 32, C_ / 32), 256>>>(w_qkv, C_, NQKV_, 0);
    tsplit_kernel<<<dim3(C_ / 32, C_ / 32), 256>>>(w_proj, C_, C_, 1);

    const int gsmem = 8 * 5120 * (int)sizeof(bf16);   // 80 KB
    cudaFuncSetAttribute(gemm_kernel<1>, cudaFuncAttributeMaxDynamicSharedMemorySize, gsmem);
    cudaFuncSetAttribute(gemm_kernel<2>, cudaFuncAttributeMaxDynamicSharedMemorySize, gsmem);
    const int fsmem = FLASH_SMEM;                      // 54 KB
    cudaFuncSetAttribute(flash_kernel, cudaFuncAttributeMaxDynamicSharedMemorySize, fsmem);

    gemm_kernel<1><<<dim3(NQKV_ / 128, M_ / 128), 256, gsmem>>>(nullptr);
    flash_kernel<<<dim3(T_ / 128, BH_), 256, fsmem>>>();
    gemm_kernel<2><<<dim3(C_ / 128, M_ / 128), 256, gsmem>>>(out);
}

// round 7
// speedup vs baseline: 1.0704x; 1.0704x over previous
#include <cuda_runtime.h>
#include <cuda_bf16.h>
#include <cuda_fp16.h>
#include <math.h>
#include <stdint.h>

#define B_  2
#define T_  4096
#define C_  768
#define H_  12
#define D_  64
#define NQKV_ 2304
#define M_  8192
#define BH_ (B_*H_)

typedef __nv_bfloat16 bf16;

// ---------------- device scratch (allocation-free rule) -------------------
__device__ __align__(16) bf16 g_xh[M_*C_],      g_xl[M_*C_];
__device__ __align__(16) bf16 g_wqkvT_h[NQKV_*C_], g_wqkvT_l[NQKV_*C_];
__device__ __align__(16) bf16 g_wpT_h[C_*C_],   g_wpT_l[C_*C_];
__device__ __align__(16) bf16 g_Qh[BH_*T_*D_],  g_Ql[BH_*T_*D_];
__device__ __align__(16) bf16 g_Kh[BH_*T_*D_],  g_Kl[BH_*T_*D_];
__device__ __align__(16) __half g_Vt[BH_*D_*T_];          // [bh][d][t]
__device__ __align__(16) bf16 g_Yh[M_*C_],      g_Yl[M_*C_];

// ---------------- helpers -------------------------------------------------
__device__ __forceinline__ void mma16816(float c[4], const uint32_t a[4], const uint32_t b[2]) {
    asm volatile("mma.sync.aligned.m16n8k16.row.col.f32.bf16.bf16.f32 "
        "{%0,%1,%2,%3}, {%4,%5,%6,%7}, {%8,%9}, {%0,%1,%2,%3};\n"
        : "+f"(c[0]), "+f"(c[1]), "+f"(c[2]), "+f"(c[3])
        : "r"(a[0]), "r"(a[1]), "r"(a[2]), "r"(a[3]), "r"(b[0]), "r"(b[1]));
}
__device__ __forceinline__ void mma16816h(float c[4], const uint32_t a[4], const uint32_t b[2]) {
    asm volatile("mma.sync.aligned.m16n8k16.row.col.f32.f16.f16.f32 "
        "{%0,%1,%2,%3}, {%4,%5,%6,%7}, {%8,%9}, {%0,%1,%2,%3};\n"
        : "+f"(c[0]), "+f"(c[1]), "+f"(c[2]), "+f"(c[3])
        : "r"(a[0]), "r"(a[1]), "r"(a[2]), "r"(a[3]), "r"(b[0]), "r"(b[1]));
}
__device__ __forceinline__ void ldsm4(uint32_t r[4], const void* p) {
    uint32_t a = (uint32_t)__cvta_generic_to_shared(p);
    asm volatile("ldmatrix.sync.aligned.m8n8.x4.shared.b16 {%0,%1,%2,%3}, [%4];"
        : "=r"(r[0]), "=r"(r[1]), "=r"(r[2]), "=r"(r[3]) : "r"(a));
}
__device__ __forceinline__ void cp16(void* dst, const void* src) {
    unsigned d = (unsigned)__cvta_generic_to_shared(dst);
    asm volatile("cp.async.cg.shared.global [%0], [%1], 16;\n" :: "r"(d), "l"(src));
}
__device__ __forceinline__ void cp_commit() { asm volatile("cp.async.commit_group;\n"); }
template<int N> __device__ __forceinline__ void cp_wait() {
    asm volatile("cp.async.wait_group %0;\n" :: "n"(N));
}
__device__ __forceinline__ void split2(float v, bf16& h, bf16& l) {
    h = __float2bfloat16(v);
    l = __float2bfloat16(v - __bfloat162float(h));
}
__device__ __forceinline__ float fast_exp2(float y) {
    y = fmaxf(y, -120.f);
    float t = y + 12582912.f;
    int   yi = __float_as_int(t) - 0x4B400000;
    float f  = y - (t - 12582912.f);
    float p = 1.3333558146e-3f;
    p = fmaf(p, f, 9.6181291076e-3f);
    p = fmaf(p, f, 5.5504108664e-2f);
    p = fmaf(p, f, 2.4022650696e-1f);
    p = fmaf(p, f, 6.9314718056e-1f);
    p = fmaf(p, f, 1.0f);
    return p * __int_as_float((yi + 127) << 23);
}
__device__ __forceinline__ void pack_split(float a, float b, uint32_t& ph, uint32_t& pl) {
    bf16 ah, al, bh, bl;
    split2(a, ah, al); split2(b, bh, bl);
    __nv_bfloat162 Hh; Hh.x = ah; Hh.y = bh;
    __nv_bfloat162 Ll; Ll.x = al; Ll.y = bl;
    ph = *(uint32_t*)&Hh; pl = *(uint32_t*)&Ll;
}

// ---------------- prep kernels -------------------------------------------
__global__ __launch_bounds__(256) void split_x_kernel(const float* __restrict__ x) {
    size_t i = ((size_t)blockIdx.x * 256 + threadIdx.x) * 4;
    float4 v = *(const float4*)(x + i);
    bf16 h0,l0,h1,l1,h2,l2,h3,l3;
    split2(v.x,h0,l0); split2(v.y,h1,l1); split2(v.z,h2,l2); split2(v.w,h3,l3);
    __nv_bfloat162 a,b,c,d;
    a.x=h0; a.y=h1; b.x=h2; b.y=h3; c.x=l0; c.y=l1; d.x=l2; d.y=l3;
    *(__nv_bfloat162*)(g_xh + i)     = a;
    *(__nv_bfloat162*)(g_xh + i + 2) = b;
    *(__nv_bfloat162*)(g_xl + i)     = c;
    *(__nv_bfloat162*)(g_xl + i + 2) = d;
}

__global__ __launch_bounds__(256) void tsplit_kernel(const float* __restrict__ w,
                                                     int K, int N, int mode) {
    __shared__ float tile[32][33];
    bf16* outh = mode == 0 ? g_wqkvT_h : g_wpT_h;
    bf16* outl = mode == 0 ? g_wqkvT_l : g_wpT_l;
    const int n0 = blockIdx.x * 32, k0 = blockIdx.y * 32;
    const int tx = threadIdx.x & 31, ty = threadIdx.x >> 5;
#pragma unroll
    for (int r = 0; r < 32; r += 8)
        tile[ty + r][tx] = w[(size_t)(k0 + ty + r) * N + n0 + tx];
    __syncthreads();
#pragma unroll
    for (int r = 0; r < 32; r += 8) {
        float v = tile[tx][ty + r];
        bf16 h, l; split2(v, h, l);
        size_t o = (size_t)(n0 + ty + r) * K + k0 + tx;
        outh[o] = h; outl[o] = l;
    }
}

// ---------------- GEMM (mma.sync, R5-proven) -------------------------------
__device__ __forceinline__ void epi_qkv(int m, int n, float v0, float v1) {
    const int b = m >> 12, t = m & 4095;
    const int sec = n / C_, r = n - sec * C_;
    const int h = r >> 6, d = r & 63;
    const int bh = b * H_ + h;
    if (sec == 2) {
        size_t o = ((size_t)bh * D_ + d) * T_ + t;
        g_Vt[o]      = __float2half(v0);
        g_Vt[o + T_] = __float2half(v1);
    } else {
        bf16 h0, l0, h1, l1;
        split2(v0, h0, l0); split2(v1, h1, l1);
        size_t o = ((size_t)bh * T_ + t) * D_ + d;
        bf16* dh = sec == 0 ? g_Qh : g_Kh;
        bf16* dl = sec == 0 ? g_Ql : g_Kl;
        __nv_bfloat162 Hh; Hh.x = h0; Hh.y = h1;
        __nv_bfloat162 Ll; Ll.x = l0; Ll.y = l1;
        *(__nv_bfloat162*)(dh + o) = Hh;
        *(__nv_bfloat162*)(dl + o) = Ll;
    }
}

template<int MODE>
__global__ __launch_bounds__(256, 2) void gemm_kernel(float* __restrict__ out) {
    extern __shared__ bf16 sm[];
    bf16* sAh = sm;
    bf16* sAl = sm + 2 * 5120;
    bf16* sBh = sm + 4 * 5120;
    bf16* sBl = sm + 6 * 5120;

    const bf16* Agh = (MODE == 1) ? g_xh : g_Yh;
    const bf16* Agl = (MODE == 1) ? g_xl : g_Yl;
    const bf16* Bgh = (MODE == 1) ? g_wqkvT_h : g_wpT_h;
    const bf16* Bgl = (MODE == 1) ? g_wqkvT_l : g_wpT_l;

    const int tid = threadIdx.x, wid = tid >> 5, lane = tid & 31;
    const int wm = wid >> 1, wn = wid & 1;
    const int lq = lane >> 2, cq = (lane & 3) << 1;
    const int bm = blockIdx.y * 128, bn = blockIdx.x * 128;

    const int a_loff = ((((lane >> 3) & 1) * 8 + (lane & 7)) * 40) + (lane >> 4) * 8;
    const int b_loff = (((lane >> 4) * 8 + (lane & 7)) * 40) + ((lane >> 3) & 1) * 8;

    float acc[2][8][4];
#pragma unroll
    for (int i = 0; i < 2; i++)
#pragma unroll
        for (int j = 0; j < 8; j++)
#pragma unroll
            for (int k = 0; k < 4; k++) acc[i][j][k] = 0.f;

#define LOAD_TILES(BUF, K0)                                                   \
    {                                                                         \
        _Pragma("unroll")                                                     \
        for (int i_ = 0; i_ < 2; i_++) {                                      \
            int c_ = tid + 256 * i_;                                          \
            int row_ = c_ >> 2;                                               \
            int ko_ = (c_ & 3) << 3;                                          \
            size_t ga_ = (size_t)(bm + row_) * C_ + (K0) + ko_;               \
            size_t gb_ = (size_t)(bn + row_) * C_ + (K0) + ko_;               \
            int so_ = (BUF) * 5120 + row_ * 40 + ko_;                         \
            cp16(sAh + so_, Agh + ga_);                                       \
            cp16(sAl + so_, Agl + ga_);                                       \
            cp16(sBh + so_, Bgh + gb_);                                       \
            cp16(sBl + so_, Bgl + gb_);                                       \
        }                                                                     \
    }

    LOAD_TILES(0, 0); cp_commit();
    int buf = 0;
    for (int kt = 0; kt < 24; kt++) {
        if (kt < 23) { LOAD_TILES(buf ^ 1, (kt + 1) * 32); cp_commit(); cp_wait<1>(); }
        else cp_wait<0>();
        __syncthreads();
#pragma unroll
        for (int kc = 0; kc < 2; kc++) {
            uint32_t ah[2][4], al[2][4];
#pragma unroll
            for (int mc = 0; mc < 2; mc++) {
                const int ao = buf * 5120 + (wm * 32 + mc * 16) * 40 + kc * 16 + a_loff;
                ldsm4(ah[mc], sAh + ao);
                ldsm4(al[mc], sAl + ao);
            }
#pragma unroll
            for (int nc2 = 0; nc2 < 4; nc2++) {
                uint32_t bh4[4], bl4[4];
                const int bo = buf * 5120 + (wn * 64 + nc2 * 16) * 40 + kc * 16 + b_loff;
                ldsm4(bh4, sBh + bo);
                ldsm4(bl4, sBl + bo);
#pragma unroll
                for (int mc = 0; mc < 2; mc++) {
                    mma16816(acc[mc][2*nc2],   ah[mc], &bh4[0]);
                    mma16816(acc[mc][2*nc2],   ah[mc], &bl4[0]);
                    mma16816(acc[mc][2*nc2],   al[mc], &bh4[0]);
                    mma16816(acc[mc][2*nc2+1], ah[mc], &bh4[2]);
                    mma16816(acc[mc][2*nc2+1], ah[mc], &bl4[2]);
                    mma16816(acc[mc][2*nc2+1], al[mc], &bh4[2]);
                }
            }
        }
        __syncthreads();
        buf ^= 1;
    }

#pragma unroll
    for (int mc = 0; mc < 2; mc++)
#pragma unroll
        for (int nc = 0; nc < 8; nc++) {
            const int m = bm + wm * 32 + mc * 16 + lq;
            const int n = bn + wn * 64 + nc * 8 + cq;
            float* a = acc[mc][nc];
            if (MODE == 2) {
                *(float2*)&out[(size_t)m * C_ + n]       = make_float2(a[0], a[1]);
                *(float2*)&out[(size_t)(m + 8) * C_ + n] = make_float2(a[2], a[3]);
            } else {
                epi_qkv(m, n, a[0], a[1]);
                epi_qkv(m + 8, n, a[2], a[3]);
            }
        }
}

// ---------------- flash attention ------------------------------------------
// 2 CTAs/SM: Q tile lives in smem (hi/lo, stride 72), fragments via ldmatrix.
#define SA_ 0.1803368801111204f
#define FSTAGE 13824                 /* per KV stage: Kh|Kl|Vt, 64 rows x 72 */
#define FQ_OFF (2 * FSTAGE)          /* Q hi at FQ_OFF, Q lo at FQ_OFF+9216 */
#define FLASH_SMEM ((2 * FSTAGE + 2 * 9216) * 2)   /* 92160 B */

__global__ __launch_bounds__(256, 2) void flash_kernel() {
    extern __shared__ bf16 fsm[];

    const int qt = (int)(gridDim.x - 1) - (int)blockIdx.x;   // heavy tiles first
    const int bh = blockIdx.y;
    const int tid = threadIdx.x, wid = tid >> 5, lane = tid & 31;
    const int lq = lane >> 2, cq = (lane & 3) << 1;
    const int row0 = qt * 128 + wid * 16 + lq;

    // per-lane ldmatrix offsets (stride 72)
    const int b_loff = (((lane >> 4) * 8 + (lane & 7)) * 72) + ((lane >> 3) & 1) * 8;
    const int a_loff = ((((lane >> 3) & 1) * 8 + (lane & 7)) * 72) + (lane >> 4) * 8;
    const int q_woff = (wid * 16) * 72;

    bf16* sQh = fsm + FQ_OFF;
    bf16* sQl = fsm + FQ_OFF + 9216;

    float oacc[8][4];
#pragma unroll
    for (int i = 0; i < 8; i++)
#pragma unroll
        for (int j = 0; j < 4; j++) oacc[i][j] = 0.f;
    float m0 = -1e30f, m1 = -1e30f, l0 = 0.f, l1 = 0.f;

    const bf16* Kb_h = g_Kh + (size_t)bh * T_ * D_;
    const bf16* Kb_l = g_Kl + (size_t)bh * T_ * D_;
    const __half* Vb = g_Vt + (size_t)bh * D_ * T_;

#define LOADF(BUF, KT)                                                        \
    {                                                                         \
        bf16* bb = fsm + (BUF) * FSTAGE;                                      \
        const bf16* ph_ = Kb_h + (size_t)(KT) * 64 * D_;                      \
        const bf16* pl_ = Kb_l + (size_t)(KT) * 64 * D_;                      \
        _Pragma("unroll")                                                     \
        for (int c_ = tid; c_ < 512; c_ += 256) {                             \
            const int r_ = c_ >> 3, of_ = (c_ & 7) << 3;                      \
            cp16(bb + r_ * 72 + of_, ph_ + r_ * D_ + of_);                    \
            cp16(bb + 4608 + r_ * 72 + of_, pl_ + r_ * D_ + of_);             \
            cp16((__half*)(bb + 9216) + r_ * 72 + of_,                        \
                 Vb + (size_t)r_ * T_ + (KT) * 64 + of_);                     \
        }                                                                     \
    }

    // Q tile -> smem (once)
    {
        const bf16* Qp_h = g_Qh + ((size_t)bh * T_ + (size_t)qt * 128) * D_;
        const bf16* Qp_l = g_Ql + ((size_t)bh * T_ + (size_t)qt * 128) * D_;
#pragma unroll
        for (int c = tid; c < 1024; c += 256) {
            const int r = c >> 3, of = (c & 7) << 3;
            cp16(sQh + r * 72 + of, Qp_h + r * D_ + of);
            cp16(sQl + r * 72 + of, Qp_l + r * D_ + of);
        }
    }

    const int nkt = 2 * qt + 2;
    LOADF(0, 0); cp_commit();
    int buf = 0;
    for (int kt = 0; kt < nkt; kt++) {
        cp_wait<0>(); __syncthreads();
        if (kt + 1 < nkt) { LOADF(buf ^ 1, kt + 1); cp_commit(); }

        const bf16* sKh = fsm + buf * FSTAGE;
        const bf16* sKl = sKh + 4608;
        const __half* sVt = (const __half*)(sKh + 9216);

        // S = Q K^T (3-term bf16 split); Q fragments via ldmatrix from smem
        float sacc[8][4];
#pragma unroll
        for (int i = 0; i < 8; i++)
#pragma unroll
            for (int j = 0; j < 4; j++) sacc[i][j] = 0.f;
#pragma unroll
        for (int kc = 0; kc < 4; kc++) {
            uint32_t qh4[4], ql4[4];
            ldsm4(qh4, sQh + q_woff + kc * 16 + a_loff);
            ldsm4(ql4, sQl + q_woff + kc * 16 + a_loff);
#pragma unroll
            for (int nc2 = 0; nc2 < 4; nc2++) {
                uint32_t kh4[4], kl4[4];
                const int o = nc2 * 16 * 72 + kc * 16 + b_loff;
                ldsm4(kh4, sKh + o);
                ldsm4(kl4, sKl + o);
                mma16816(sacc[2*nc2],   qh4, &kh4[0]);
                mma16816(sacc[2*nc2],   qh4, &kl4[0]);
                mma16816(sacc[2*nc2],   ql4, &kh4[0]);
                mma16816(sacc[2*nc2+1], qh4, &kh4[2]);
                mma16816(sacc[2*nc2+1], qh4, &kl4[2]);
                mma16816(sacc[2*nc2+1], ql4, &kh4[2]);
            }
        }

        // causal mask
        if (kt >= 2 * qt) {
            const int colb = kt * 64;
#pragma unroll
            for (int nc = 0; nc < 8; nc++) {
                const int c0 = colb + nc * 8 + cq;
                if (c0     > row0)     sacc[nc][0] = -1e30f;
                if (c0 + 1 > row0)     sacc[nc][1] = -1e30f;
                if (c0     > row0 + 8) sacc[nc][2] = -1e30f;
                if (c0 + 1 > row0 + 8) sacc[nc][3] = -1e30f;
            }
        }

        // online softmax
        float mx0 = -1e30f, mx1 = -1e30f;
#pragma unroll
        for (int nc = 0; nc < 8; nc++) {
            mx0 = fmaxf(mx0, fmaxf(sacc[nc][0], sacc[nc][1]));
            mx1 = fmaxf(mx1, fmaxf(sacc[nc][2], sacc[nc][3]));
        }
        mx0 = fmaxf(mx0, __shfl_xor_sync(0xffffffffu, mx0, 1));
        mx0 = fmaxf(mx0, __shfl_xor_sync(0xffffffffu, mx0, 2));
        mx1 = fmaxf(mx1, __shfl_xor_sync(0xffffffffu, mx1, 1));
        mx1 = fmaxf(mx1, __shfl_xor_sync(0xffffffffu, mx1, 2));
        const float mn0 = fmaxf(m0, mx0), mn1 = fmaxf(m1, mx1);
        const float sc0 = fast_exp2((m0 - mn0) * SA_);
        const float sc1 = fast_exp2((m1 - mn1) * SA_);
        m0 = mn0; m1 = mn1;
        l0 *= sc0; l1 *= sc1;
#pragma unroll
        for (int dc = 0; dc < 8; dc++) {
            oacc[dc][0] *= sc0; oacc[dc][1] *= sc0;
            oacc[dc][2] *= sc1; oacc[dc][3] *= sc1;
        }

        // P = exp(S - m) -> fp16 A fragments
        uint32_t pa[4][4];
#pragma unroll
        for (int kc = 0; kc < 4; kc++) {
            const float e0 = fast_exp2((sacc[2*kc][0]   - m0) * SA_);
            const float e1 = fast_exp2((sacc[2*kc][1]   - m0) * SA_);
            const float e2 = fast_exp2((sacc[2*kc][2]   - m1) * SA_);
            const float e3 = fast_exp2((sacc[2*kc][3]   - m1) * SA_);
            const float f0 = fast_exp2((sacc[2*kc+1][0] - m0) * SA_);
            const float f1 = fast_exp2((sacc[2*kc+1][1] - m0) * SA_);
            const float f2 = fast_exp2((sacc[2*kc+1][2] - m1) * SA_);
            const float f3 = fast_exp2((sacc[2*kc+1][3] - m1) * SA_);
            l0 += e0 + e1 + f0 + f1;
            l1 += e2 + e3 + f2 + f3;
            __half2 t0 = __floats2half2_rn(e0, e1);
            __half2 t1 = __floats2half2_rn(e2, e3);
            __half2 t2 = __floats2half2_rn(f0, f1);
            __half2 t3 = __floats2half2_rn(f2, f3);
            pa[kc][0] = *(uint32_t*)&t0;
            pa[kc][1] = *(uint32_t*)&t1;
            pa[kc][2] = *(uint32_t*)&t2;
            pa[kc][3] = *(uint32_t*)&t3;
        }

        // O += P V (single fp16 mma), V fragments via ldmatrix
#pragma unroll
        for (int kc = 0; kc < 4; kc++) {
#pragma unroll
            for (int dc2 = 0; dc2 < 4; dc2++) {
                uint32_t v4[4];
                ldsm4(v4, sVt + dc2 * 16 * 72 + kc * 16 + b_loff);
                mma16816h(oacc[2*dc2],   pa[kc], &v4[0]);
                mma16816h(oacc[2*dc2+1], pa[kc], &v4[2]);
            }
        }
        __syncthreads();
        buf ^= 1;
    }

    // finalize
    l0 += __shfl_xor_sync(0xffffffffu, l0, 1);
    l0 += __shfl_xor_sync(0xffffffffu, l0, 2);
    l1 += __shfl_xor_sync(0xffffffffu, l1, 1);
    l1 += __shfl_xor_sync(0xffffffffu, l1, 2);
    const float inv0 = 1.f / l0, inv1 = 1.f / l1;

    const int b = bh / H_, h = bh - b * H_;
    const size_t y0 = ((size_t)b * T_ + row0) * C_ + h * D_;
    const size_t y1 = ((size_t)b * T_ + row0 + 8) * C_ + h * D_;
#pragma unroll
    for (int dc = 0; dc < 8; dc++) {
        const int col = dc * 8 + cq;
        uint32_t ph, pl;
        pack_split(oacc[dc][0] * inv0, oacc[dc][1] * inv0, ph, pl);
        *(uint32_t*)(g_Yh + y0 + col) = ph;
        *(uint32_t*)(g_Yl + y0 + col) = pl;
        pack_split(oacc[dc][2] * inv1, oacc[dc][3] * inv1, ph, pl);
        *(uint32_t*)(g_Yh + y1 + col) = ph;
        *(uint32_t*)(g_Yl + y1 + col) = pl;
    }
}

// ---------------------------------------------------------------------------
extern "C" void kernel_launch(void* const* d_in, const int* in_sizes, int n_in,
                              void* d_out, int out_size)
{
    const float* x      = (const float*)d_in[0];
    const float* w_qkv  = (const float*)d_in[1];
    const float* w_proj = (const float*)d_in[2];
    float* out = (float*)d_out;

    split_x_kernel<<<(M_ * C_) / (256 * 4), 256>>>(x);
    tsplit_kernel<<<dim3(NQKV_ / 32, C_ / 32), 256>>>(w_qkv, C_, NQKV_, 0);
    tsplit_kernel<<<dim3(C_ / 32, C_ / 32), 256>>>(w_proj, C_, C_, 1);

    const int gsmem = 8 * 5120 * (int)sizeof(bf16);   // 80 KB
    cudaFuncSetAttribute(gemm_kernel<1>, cudaFuncAttributeMaxDynamicSharedMemorySize, gsmem);
    cudaFuncSetAttribute(gemm_kernel<2>, cudaFuncAttributeMaxDynamicSharedMemorySize, gsmem);
    cudaFuncSetAttribute(flash_kernel, cudaFuncAttributeMaxDynamicSharedMemorySize, FLASH_SMEM);

    gemm_kernel<1><<<dim3(NQKV_ / 128, M_ / 128), 256, gsmem>>>(nullptr);
    flash_kernel<<<dim3(T_ / 128, BH_), 256, FLASH_SMEM>>>();
    gemm_kernel<2><<<dim3(C_ / 128, M_ / 128), 256, gsmem>>>(out);
}